// round 8
// baseline (speedup 1.0000x reference)
#include <cuda_runtime.h>
#include <cuda_fp16.h>
#include <cuda_bf16.h>
#include <cstdint>

#define NN   100000
#define EE   3200000
#define FIN  512
#define HH   64
#define CC   8

// ---------------- scratch (device globals; no runtime allocation) ----------
__device__ __half g_h1h[NN * HH];     // fp16( dinv[row] * (x @ W1) )
__device__ float g_t2[NN * CC];       // dinv[d] * (relu(agg1 + b1) @ W2)
__device__ int   g_deg[NN];
__device__ float g_dinv[NN];
__device__ int   g_rowptr[NN + 1];
__device__ int   g_cursor[NN];
__device__ int   g_col[EE];
__device__ int   g_bsum[512];
__device__ int   g_boff[512];

// W1 pre-transposed to MMA-B layout: [chunk(8)][n(64)][PADK(72)] bf16, hi & lo
#define PADK 72
__device__ __nv_bfloat16 g_w1t_hi[8 * HH * PADK];
__device__ __nv_bfloat16 g_w1t_lo[8 * HH * PADK];

// ---------------- stream fork/join infra (host, created at load) ------------
static cudaStream_t g_s2 = nullptr;
static cudaEvent_t  g_evA = nullptr, g_evB = nullptr, g_evC = nullptr;
namespace {
struct StreamInit {
    StreamInit() {
        if (cudaStreamCreateWithFlags(&g_s2, cudaStreamNonBlocking) != cudaSuccess)
            g_s2 = nullptr;
        if (g_s2) {
            if (cudaEventCreateWithFlags(&g_evA, cudaEventDisableTiming) != cudaSuccess ||
                cudaEventCreateWithFlags(&g_evB, cudaEventDisableTiming) != cudaSuccess ||
                cudaEventCreateWithFlags(&g_evC, cudaEventDisableTiming) != cudaSuccess) {
                g_s2 = nullptr;
            }
        }
    }
};
StreamInit g_stream_init;
}

// ---------------- CSR construction ------------------------------------------
__global__ void k_hist(const int* __restrict__ dst, int e) {
    int i = blockIdx.x * blockDim.x + threadIdx.x;
    if (i < e) atomicAdd(&g_deg[dst[i]], 1);
}

__global__ void k_dinv(int n) {
    int i = blockIdx.x * blockDim.x + threadIdx.x;
    if (i < n) g_dinv[i] = rsqrtf((float)(g_deg[i] + 1));
}

__global__ void k_bsum(int n) {
    __shared__ int s[256];
    int t = threadIdx.x;
    int i = blockIdx.x * 256 + t;
    s[t] = (i < n) ? g_deg[i] : 0;
    __syncthreads();
    for (int o = 128; o > 0; o >>= 1) {
        if (t < o) s[t] += s[t + o];
        __syncthreads();
    }
    if (t == 0) g_bsum[blockIdx.x] = s[0];
}

__global__ void k_scan_bsum(int nb) {
    __shared__ int s[512];
    int t = threadIdx.x;
    int v = (t < nb) ? g_bsum[t] : 0;
    s[t] = v;
    __syncthreads();
    for (int o = 1; o < 512; o <<= 1) {
        int a = (t >= o) ? s[t - o] : 0;
        __syncthreads();
        s[t] += a;
        __syncthreads();
    }
    if (t < nb) g_boff[t] = s[t] - v;
}

__global__ void k_scan_final(int n, int e) {
    __shared__ int s[256];
    int t = threadIdx.x;
    int i = blockIdx.x * 256 + t;
    int v = (i < n) ? g_deg[i] : 0;
    s[t] = v;
    __syncthreads();
    for (int o = 1; o < 256; o <<= 1) {
        int a = (t >= o) ? s[t - o] : 0;
        __syncthreads();
        s[t] += a;
        __syncthreads();
    }
    if (i < n) {
        int excl = g_boff[blockIdx.x] + s[t] - v;
        g_rowptr[i] = excl;
        g_cursor[i] = excl;
    }
    if (i == 0) g_rowptr[n] = e;
}

__global__ void k_scatter(const int* __restrict__ src,
                          const int* __restrict__ dst, int e) {
    int i = blockIdx.x * blockDim.x + threadIdx.x;
    if (i < e) {
        int d   = dst[i];
        int pos = atomicAdd(&g_cursor[d], 1);
        g_col[pos] = src[i];
    }
}

// ---------------- W1 -> bf16 hi/lo transposed image -------------------------
__global__ void k_prep_w1(const float* __restrict__ W1) {
    int idx = blockIdx.x * 256 + threadIdx.x;      // n*512 + kg
    if (idx >= HH * FIN) return;
    int nn = idx >> 9;
    int kg = idx & 511;
    float v = W1[(size_t)kg * HH + nn];
    __nv_bfloat16 hi = __float2bfloat16(v);
    __nv_bfloat16 lo = __float2bfloat16(v - __bfloat162float(hi));
    int chunk = kg >> 6, k = kg & 63;
    int o = (chunk * HH + nn) * PADK + k;
    g_w1t_hi[o] = hi;
    g_w1t_lo[o] = lo;
}

// ---------------- GEMM1: h1' = fp16(dinv * (x @ W1)) via HMMA bf16 split ----
__device__ __forceinline__ void mma16816(float* c, uint32_t a0, uint32_t a1,
                                         uint32_t a2, uint32_t a3,
                                         uint32_t b0, uint32_t b1) {
    asm volatile(
        "mma.sync.aligned.m16n8k16.row.col.f32.bf16.bf16.f32 "
        "{%0,%1,%2,%3}, {%4,%5,%6,%7}, {%8,%9}, {%0,%1,%2,%3};"
        : "+f"(c[0]), "+f"(c[1]), "+f"(c[2]), "+f"(c[3])
        : "r"(a0), "r"(a1), "r"(a2), "r"(a3), "r"(b0), "r"(b1));
}

__device__ __forceinline__ uint32_t bf16x2_rn(float up, float lo) {
    uint32_t r;
    asm("cvt.rn.bf16x2.f32 %0, %1, %2;" : "=r"(r) : "f"(up), "f"(lo));
    return r;
}

#define SM_AHI 0
#define SM_ALO (128 * PADK)
#define SM_BHI (256 * PADK)
#define SM_BLO (320 * PADK)
#define SMEM_GEMM ((384 * PADK) * 2)

__global__ __launch_bounds__(256) void k_gemm1_mma(const float* __restrict__ x,
                                                   int n) {
    extern __shared__ __nv_bfloat16 sm[];
    int tid = threadIdx.x, wid = tid >> 5, lane = tid & 31;
    int g = lane >> 2, t = lane & 3;
    int mBase = blockIdx.x * 128;

    float acc[8][4];
#pragma unroll
    for (int i = 0; i < 8; i++)
#pragma unroll
        for (int j = 0; j < 4; j++) acc[i][j] = 0.f;

    for (int chunk = 0; chunk < FIN / 64; chunk++) {
        int kb = chunk * 64;
        if (chunk) __syncthreads();

        // ---- A tile: 128 rows x 64 k from x (fp32), split hi/lo (bf16x2 cvt)
#pragma unroll
        for (int l = 0; l < 8; l++) {
            int id  = tid + l * 256;
            int row = id >> 4;
            int col = (id & 15) * 4;
            float4 v = make_float4(0.f, 0.f, 0.f, 0.f);
            int gr = mBase + row;
            if (gr < n) v = *(const float4*)&x[(size_t)gr * FIN + kb + col];
            uint32_t uh0 = bf16x2_rn(v.y, v.x);
            uint32_t uh1 = bf16x2_rn(v.w, v.z);
            float h0f = __uint_as_float(uh0 << 16);
            float h1f = __uint_as_float(uh0 & 0xFFFF0000u);
            float h2f = __uint_as_float(uh1 << 16);
            float h3f = __uint_as_float(uh1 & 0xFFFF0000u);
            uint32_t ul0 = bf16x2_rn(v.y - h1f, v.x - h0f);
            uint32_t ul1 = bf16x2_rn(v.w - h3f, v.z - h2f);
            int o = row * PADK + col;
            *(uint2*)&sm[SM_AHI + o] = make_uint2(uh0, uh1);
            *(uint2*)&sm[SM_ALO + o] = make_uint2(ul0, ul1);
        }

        // ---- B tile: contiguous copy of pre-transposed image
        {
            const uint4* shi = (const uint4*)&g_w1t_hi[chunk * HH * PADK];
            const uint4* slo = (const uint4*)&g_w1t_lo[chunk * HH * PADK];
            uint4* dhi = (uint4*)&sm[SM_BHI];
            uint4* dlo = (uint4*)&sm[SM_BLO];
            for (int i = tid; i < HH * PADK / 8; i += 256) {
                dhi[i] = shi[i];
                dlo[i] = slo[i];
            }
        }
        __syncthreads();

#pragma unroll
        for (int ks = 0; ks < 4; ks++) {
            int k0 = ks * 16;
            const __nv_bfloat16* ah = &sm[SM_AHI + (wid * 16 + g) * PADK + k0 + t * 2];
            const __nv_bfloat16* al = &sm[SM_ALO + (wid * 16 + g) * PADK + k0 + t * 2];
            uint32_t ah0 = *(const uint32_t*)ah;
            uint32_t ah1 = *(const uint32_t*)(ah + 8 * PADK);
            uint32_t ah2 = *(const uint32_t*)(ah + 8);
            uint32_t ah3 = *(const uint32_t*)(ah + 8 * PADK + 8);
            uint32_t al0 = *(const uint32_t*)al;
            uint32_t al1 = *(const uint32_t*)(al + 8 * PADK);
            uint32_t al2 = *(const uint32_t*)(al + 8);
            uint32_t al3 = *(const uint32_t*)(al + 8 * PADK + 8);
#pragma unroll
            for (int nt = 0; nt < 8; nt++) {
                const __nv_bfloat16* bh = &sm[SM_BHI + (nt * 8 + g) * PADK + k0 + t * 2];
                const __nv_bfloat16* bl = &sm[SM_BLO + (nt * 8 + g) * PADK + k0 + t * 2];
                uint32_t bh0 = *(const uint32_t*)bh;
                uint32_t bh1 = *(const uint32_t*)(bh + 8);
                uint32_t bl0 = *(const uint32_t*)bl;
                uint32_t bl1 = *(const uint32_t*)(bl + 8);
                mma16816(acc[nt], ah0, ah1, ah2, ah3, bh0, bh1);
                mma16816(acc[nt], ah0, ah1, ah2, ah3, bl0, bl1);
                mma16816(acc[nt], al0, al1, al2, al3, bh0, bh1);
            }
        }
    }

    // ---- epilogue: emit fp16 h1' = dinv[row] * h1
    int r0 = mBase + wid * 16 + g;
    float s0 = (r0 < n)     ? g_dinv[r0]     : 0.f;
    float s1 = (r0 + 8 < n) ? g_dinv[r0 + 8] : 0.f;
#pragma unroll
    for (int nt = 0; nt < 8; nt++) {
        int col = nt * 8 + t * 2;
        if (r0 < n)
            *(__half2*)&g_h1h[(size_t)r0 * HH + col] =
                __floats2half2_rn(s0 * acc[nt][0], s0 * acc[nt][1]);
        if (r0 + 8 < n)
            *(__half2*)&g_h1h[(size_t)(r0 + 8) * HH + col] =
                __floats2half2_rn(s1 * acc[nt][2], s1 * acc[nt][3]);
    }
}

// ---------------- layer-1 aggregate + bias + ReLU + @W2 ---------------------
// warp per dst; lane owns half2 slot 'lane'. h1' is pre-scaled by dinv, so the
// neighbor sum is weightless; edge indices broadcast lane->all via shfl.
__global__ __launch_bounds__(256) void k_agg1(const float* __restrict__ b1,
                                              const float* __restrict__ W2,
                                              int n) {
    __shared__ float b1s[HH];
    __shared__ float w2t[CC * HH];

    int tid = threadIdx.x;
    if (tid < HH) b1s[tid] = b1[tid];
    for (int i = tid; i < CC * HH; i += 256) {
        int c = i >> 6, k = i & 63;
        w2t[i] = W2[k * CC + c];
    }
    __syncthreads();

    int warp = tid >> 5, lane = tid & 31;
    int d = blockIdx.x * 8 + warp;
    if (d >= n) return;

    float dd = g_dinv[d];
    const __half2* h2 = (const __half2*)g_h1h;

    float2 self = __half22float2(h2[(size_t)d * 32 + lane]);   // = dd*h[d]
    float2 acc = self;

    int e0 = g_rowptr[d];
    int e1 = g_rowptr[d + 1];
    for (int base = e0; base < e1; base += 32) {
        int cnt = min(32, e1 - base);
        int sidx = (lane < cnt) ? g_col[base + lane] : 0;   // coalesced
        int j = 0;
        for (; j + 4 <= cnt; j += 4) {
            int s0 = __shfl_sync(0xffffffffu, sidx, j);
            int s1 = __shfl_sync(0xffffffffu, sidx, j + 1);
            int s2 = __shfl_sync(0xffffffffu, sidx, j + 2);
            int s3 = __shfl_sync(0xffffffffu, sidx, j + 3);
            float2 v0 = __half22float2(h2[(size_t)s0 * 32 + lane]);
            float2 v1 = __half22float2(h2[(size_t)s1 * 32 + lane]);
            float2 v2 = __half22float2(h2[(size_t)s2 * 32 + lane]);
            float2 v3 = __half22float2(h2[(size_t)s3 * 32 + lane]);
            acc.x += (v0.x + v1.x) + (v2.x + v3.x);
            acc.y += (v0.y + v1.y) + (v2.y + v3.y);
        }
        for (; j < cnt; j++) {
            int s = __shfl_sync(0xffffffffu, sidx, j);
            float2 v = __half22float2(h2[(size_t)s * 32 + lane]);
            acc.x += v.x;
            acc.y += v.y;
        }
    }

    float hx = fmaxf(dd * acc.x + b1s[2 * lane], 0.f);
    float hy = fmaxf(dd * acc.y + b1s[2 * lane + 1], 0.f);

    float pw[8];
#pragma unroll
    for (int c = 0; c < 8; c++) {
        float2 q = *(float2*)&w2t[c * HH + 2 * lane];
        pw[c] = hx * q.x + hy * q.y;
    }
#pragma unroll
    for (int c = 0; c < 8; c++) {
        pw[c] += __shfl_down_sync(0xffffffffu, pw[c], 16);
        pw[c] += __shfl_down_sync(0xffffffffu, pw[c], 8);
        pw[c] += __shfl_down_sync(0xffffffffu, pw[c], 4);
        pw[c] += __shfl_down_sync(0xffffffffu, pw[c], 2);
        pw[c] += __shfl_down_sync(0xffffffffu, pw[c], 1);
    }
    if (lane == 0) {
        // store t2' = dinv[d] * (relu(h) @ W2)  (pre-scaled for layer 2)
        *(float4*)&g_t2[(size_t)d * CC] =
            make_float4(dd * pw[0], dd * pw[1], dd * pw[2], dd * pw[3]);
        *(float4*)&g_t2[(size_t)d * CC + 4] =
            make_float4(dd * pw[4], dd * pw[5], dd * pw[6], dd * pw[7]);
    }
}

// ---------------- layer-2 aggregate + b2 -> out ------------------------------
// out[d] = dd * (sum_edges t2'[s] + t2'[d]) + b2 ; cols staged lane-parallel
// lane = j*8 + c; lane-j walks slots {j, j+4, j+8, ...} (stride 4, exhaustive)
__global__ __launch_bounds__(256) void k_agg2(const float* __restrict__ b2,
                                              float* __restrict__ out, int n) {
    __shared__ int sc[8][32];

    int tid  = threadIdx.x;
    int warp = tid >> 5, lane = tid & 31;
    int d = blockIdx.x * 8 + warp;
    if (d >= n) return;
    int j = lane >> 3, c = lane & 7;

    float dd  = g_dinv[d];
    int e0 = g_rowptr[d];
    int e1 = g_rowptr[d + 1];
    float acc = 0.f;
    for (int base = e0; base < e1; base += 32) {
        int cnt = min(32, e1 - base);
        if (lane < cnt) sc[warp][lane] = g_col[base + lane];
        __syncwarp();
        int q = j;
        for (; q + 8 <= cnt; q += 8) {
            int s0 = sc[warp][q];
            int s1 = sc[warp][q + 4];
            float u0 = g_t2[(size_t)s0 * CC + c];
            float u1 = g_t2[(size_t)s1 * CC + c];
            acc += u0 + u1;
        }
        for (; q < cnt; q += 4)                 // exhaustive stride-4 tail
            acc += g_t2[(size_t)sc[warp][q] * CC + c];
        __syncwarp();
    }
    acc += __shfl_down_sync(0xffffffffu, acc, 16);
    acc += __shfl_down_sync(0xffffffffu, acc, 8);
    if (j == 0) {
        float r = dd * (acc + g_t2[(size_t)d * CC + c]) + b2[c];
        out[(size_t)d * CC + c] = r;
    }
}

// ---------------- launch ------------------------------------------------------
extern "C" void kernel_launch(void* const* d_in, const int* in_sizes, int n_in,
                              void* d_out, int out_size) {
    const float* x  = (const float*)d_in[0];
    const int*   ei = (const int*)d_in[1];
    const float* W1 = (const float*)d_in[2];
    const float* b1 = (const float*)d_in[3];
    const float* W2 = (const float*)d_in[4];
    const float* b2 = (const float*)d_in[5];

    int n = in_sizes[0] / FIN;   // 100000
    int e = in_sizes[1] / 2;     // 3200000
    const int* src = ei;
    const int* dst = ei + e;

    int nb = (n + 255) / 256;

    cudaFuncSetAttribute(k_gemm1_mma, cudaFuncAttributeMaxDynamicSharedMemorySize,
                         SMEM_GEMM);

    void* degAddr = nullptr;
    cudaGetSymbolAddress(&degAddr, g_deg);

    if (g_s2) {
        // fork: prep_w1 can start immediately on s2
        cudaEventRecord(g_evA, 0);
        cudaStreamWaitEvent(g_s2, g_evA, 0);
        k_prep_w1<<<(HH * FIN + 255) / 256, 256, 0, g_s2>>>(W1);

        // main: deg -> dinv (GEMM epilogue dependency)
        cudaMemsetAsync(degAddr, 0, (size_t)n * sizeof(int), 0);
        k_hist<<<(e + 255) / 256, 256>>>(dst, e);
        k_dinv<<<nb, 256>>>(n);
        cudaEventRecord(g_evC, 0);

        // s2: GEMM (waits for dinv)
        cudaStreamWaitEvent(g_s2, g_evC, 0);
        k_gemm1_mma<<<(n + 127) / 128, 256, SMEM_GEMM, g_s2>>>(x, n);
        cudaEventRecord(g_evB, g_s2);

        // main: rest of CSR build in parallel with GEMM
        k_bsum<<<nb, 256>>>(n);
        k_scan_bsum<<<1, 512>>>(nb);
        k_scan_final<<<nb, 256>>>(n, e);
        k_scatter<<<(e + 255) / 256, 256>>>(src, dst, e);

        cudaStreamWaitEvent(0, g_evB, 0);   // join
    } else {
        cudaMemsetAsync(degAddr, 0, (size_t)n * sizeof(int), 0);
        k_hist<<<(e + 255) / 256, 256>>>(dst, e);
        k_dinv<<<nb, 256>>>(n);
        k_bsum<<<nb, 256>>>(n);
        k_scan_bsum<<<1, 512>>>(nb);
        k_scan_final<<<nb, 256>>>(n, e);
        k_scatter<<<(e + 255) / 256, 256>>>(src, dst, e);
        k_prep_w1<<<(HH * FIN + 255) / 256, 256>>>(W1);
        k_gemm1_mma<<<(n + 127) / 128, 256, SMEM_GEMM>>>(x, n);
    }

    k_agg1<<<(n + 7) / 8, 256>>>(b1, W2, n);
    k_agg2<<<(n + 7) / 8, 256>>>(b2, (float*)d_out, n);
}